// round 7
// baseline (speedup 1.0000x reference)
#include <cuda_runtime.h>

// DihedralToCartesian R7: segmented decomposition (14 x 9) with a PARALLEL
// Hillis-Steele scan over rigid transforms (R6's serial 13-iter compose was
// the regression cause). Angle normalization hoisted into the parallel load
// phase: buf holds (r1, r2) = (sin_a*cos_t, -sin_a*sin_t)*invn per step, so
// the serial chain per step loses a rsqrt. Exclusive prefix via identity
// slot; all 224 threads active in every phase.

#define TPB    224
#define NRES   126
#define CHAINS 16
#define SEG    14
#define LSEG   9

__device__ __forceinline__ float frsqrt(float x) {
    float y;
    asm("rsqrt.approx.f32 %0, %1;" : "=f"(y) : "f"(x));
    return y;
}

__global__ void __launch_bounds__(TPB, 6)
dihedral_kernel(const float* __restrict__ angles,
                const float* __restrict__ prev,
                float* __restrict__ out)
{
    // buf record (3 floats per step): (r1, r2, -) on load -> local points.
    __shared__ float buf[CHAINS * NRES * 3];            // 24192 B
    __shared__ float mat[CHAINS * (SEG + 1) * 12];      // 11520 B: slot0=identity

    const int tid   = threadIdx.x;
    const int c     = tid / SEG;
    const int s     = tid - c * SEG;
    const int Bbase = blockIdx.x * CHAINS;

    // compile-time constants
    const float CA0 = cosf(2.028f), SA0 = sinf(2.028f), B0 = 1.329f;
    const float CA1 = cosf(2.124f), SA1 = sinf(2.124f), B1 = 1.458f;
    const float CA2 = cosf(1.941f), SA2 = sinf(1.941f), B2 = 1.523f;

    // ---- phase 0: coalesced load + angle normalization (parallel) ----
    const float* gang = angles + (size_t)Bbase * (2 * NRES);
    #pragma unroll
    for (int i = 0; i < (CHAINS * NRES) / TPB; ++i) {   // 9 iters
        int e  = tid + i * TPB;
        int cc = e / NRES;
        int j  = e - cc * NRES;
        int k  = j - (j / 3) * 3;
        float sn = gang[cc * (2 * NRES) + j];
        float co = gang[cc * (2 * NRES) + NRES + j];
        float sa = (k == 0) ? SA0 : (k == 1) ? SA1 : SA2;
        float t  = sa * frsqrt(fmaf(sn, sn, fmaf(co, co, 1e-8f)));
        buf[e * 3 + 0] =  t * co;   // r1
        buf[e * 3 + 1] = -t * sn;   // r2
    }
    __syncthreads();

    // ---- phase 1: LSEG steps locally (serial chain, per segment) ----
    float* rec = &buf[(c * NRES + s * LSEG) * 3];
    float px, py, pz, vx, vy, vz, wx, wy, wz;

    #define STEP(j, CAk, Bk) do {                                               \
        float r1 = rec[(j) * 3 + 0], r2 = rec[(j) * 3 + 1];                     \
        float cxx = wy * vz - wz * vy;                                          \
        float cxy = wz * vx - wx * vz;                                          \
        float cxz = wx * vy - wy * vx;                                          \
        float inr = frsqrt(fmaf(cxx, cxx, fmaf(cxy, cxy,                        \
                                fmaf(cxz, cxz, 1e-20f))));                      \
        float nx = cxx * inr, ny = cxy * inr, nz = cxz * inr;                   \
        float mx = wy * nz - wz * ny;                                           \
        float my = wz * nx - wx * nz;                                           \
        float mz = wx * ny - wy * nx;                                           \
        float ux = fmaf(-(CAk), wx, fmaf(r1, mx, r2 * nx));                     \
        float uy = fmaf(-(CAk), wy, fmaf(r1, my, r2 * ny));                     \
        float uz = fmaf(-(CAk), wz, fmaf(r1, mz, r2 * nz));                     \
        px = fmaf((Bk), ux, px);                                                \
        py = fmaf((Bk), uy, py);                                                \
        pz = fmaf((Bk), uz, pz);                                                \
        rec[(j) * 3 + 0] = px;                                                  \
        rec[(j) * 3 + 1] = py;                                                  \
        rec[(j) * 3 + 2] = pz;                                                  \
        float iun = frsqrt(fmaf(ux, ux, fmaf(uy, uy, uz * uz)));                \
        vx = wx; vy = wy; vz = wz;                                              \
        wx = ux * iun; wy = uy * iun; wz = uz * iun;                            \
    } while (0)

    if (s == 0) {
        // real geometry from prev_three; reference-faithful first step
        const float* pp = prev + (size_t)(Bbase + c) * 9;
        float ax = pp[0], ay = pp[1], az = pp[2];
        float bx = pp[3], by = pp[4], bz = pp[5];
        px = pp[6]; py = pp[7]; pz = pp[8];

        float r1 = rec[0], r2 = rec[1];

        float bcx = (bx - px) + 1e-8f;
        float bcy = (by - py) + 1e-8f;
        float bcz = (bz - pz) + 1e-8f;
        float ib = frsqrt(fmaf(bcx, bcx, fmaf(bcy, bcy, bcz * bcz)));
        bcx *= ib; bcy *= ib; bcz *= ib;

        float qx = bx - ax, qy = by - ay, qz = bz - az;
        float nx = fmaf(qy, bcz, fmaf(-qz, bcy, 1e-8f));
        float ny = fmaf(qz, bcx, fmaf(-qx, bcz, 1e-8f));
        float nz = fmaf(qx, bcy, fmaf(-qy, bcx, 1e-8f));
        float in_ = frsqrt(fmaf(nx, nx, fmaf(ny, ny, nz * nz)));
        nx *= in_; ny *= in_; nz *= in_;

        float mx = ny * bcz - nz * bcy;
        float my = nz * bcx - nx * bcz;
        float mz = nx * bcy - ny * bcx;

        float ux = fmaf(CA0, bcx, fmaf(r1, mx, r2 * nx));
        float uy = fmaf(CA0, bcy, fmaf(r1, my, r2 * ny));
        float uz = fmaf(CA0, bcz, fmaf(r1, mz, r2 * nz));

        px = fmaf(B0, ux, px);
        py = fmaf(B0, uy, py);
        pz = fmaf(B0, uz, pz);
        rec[0] = px; rec[1] = py; rec[2] = pz;

        float iun = frsqrt(fmaf(ux, ux, fmaf(uy, uy, uz * uz)));
        vx = -bcx; vy = -bcy; vz = -bcz;
        wx = ux * iun; wy = uy * iun; wz = uz * iun;
    } else {
        // canonical entry frame (boundary geometry is constant: i0 % 3 == 0)
        px = 0.f; py = 0.f; pz = 0.f;
        wx = 1.f; wy = 0.f; wz = 0.f;
        vx = -CA2; vy = SA2; vz = 0.f;
        STEP(0, CA0, B0);
    }
    STEP(1, CA1, B1); STEP(2, CA2, B2);
    STEP(3, CA0, B0); STEP(4, CA1, B1); STEP(5, CA2, B2);
    STEP(6, CA0, B0); STEP(7, CA1, B1); STEP(8, CA2, B2);
    #undef STEP

    // ---- phase 2: local rigid map M_s = (GS(w,v) | p), then parallel scan --
    // prefix in registers: R columns a1,a2,a3 and translation ap.
    float a1x, a1y, a1z, a2x, a2y, a2z, a3x, a3y, a3z, apx, apy, apz;
    {
        float d  = fmaf(vx, wx, fmaf(vy, wy, vz * wz));
        float tx = fmaf(-d, wx, vx);
        float ty = fmaf(-d, wy, vy);
        float tz = fmaf(-d, wz, vz);
        float it = frsqrt(fmaf(tx, tx, fmaf(ty, ty, fmaf(tz, tz, 1e-20f))));
        a1x = wx;      a1y = wy;      a1z = wz;
        a2x = tx * it; a2y = ty * it; a2z = tz * it;
        a3x = a1y * a2z - a1z * a2y;
        a3y = a1z * a2x - a1x * a2z;
        a3z = a1x * a2y - a1y * a2x;
        apx = px; apy = py; apz = pz;
    }

    float* mslot = &mat[(c * (SEG + 1) + s + 1) * 12];

    #pragma unroll
    for (int off = 1; off < SEG; off <<= 1) {           // 1, 2, 4, 8
        mslot[0] = a1x; mslot[1]  = a1y; mslot[2]  = a1z;
        mslot[3] = a2x; mslot[4]  = a2y; mslot[5]  = a2z;
        mslot[6] = a3x; mslot[7]  = a3y; mslot[8]  = a3z;
        mslot[9] = apx; mslot[10] = apy; mslot[11] = apz;
        __syncthreads();
        float b1x=0, b1y=0, b1z=0, b2x=0, b2y=0, b2z=0;
        float b3x=0, b3y=0, b3z=0, bpx=0, bpy=0, bpz=0;
        if (s >= off) {
            const float* L = &mat[(c * (SEG + 1) + s + 1 - off) * 12];
            b1x = L[0]; b1y = L[1];  b1z = L[2];
            b2x = L[3]; b2y = L[4];  b2z = L[5];
            b3x = L[6]; b3y = L[7];  b3z = L[8];
            bpx = L[9]; bpy = L[10]; bpz = L[11];
        }
        __syncthreads();
        if (s >= off) {
            // prefix = L  o  prefix : cols' = L.R * cols, p' = L.R*p + L.p
            float n1x = a1x*b1x + a1y*b2x + a1z*b3x;
            float n1y = a1x*b1y + a1y*b2y + a1z*b3y;
            float n1z = a1x*b1z + a1y*b2z + a1z*b3z;
            float n2x = a2x*b1x + a2y*b2x + a2z*b3x;
            float n2y = a2x*b1y + a2y*b2y + a2z*b3y;
            float n2z = a2x*b1z + a2y*b2z + a2z*b3z;
            float n3x = a3x*b1x + a3y*b2x + a3z*b3x;
            float n3y = a3x*b1y + a3y*b2y + a3z*b3y;
            float n3z = a3x*b1z + a3y*b2z + a3z*b3z;
            float npx = apx*b1x + apy*b2x + apz*b3x + bpx;
            float npy = apx*b1y + apy*b2y + apz*b3y + bpy;
            float npz = apx*b1z + apy*b2z + apz*b3z + bpz;
            a1x=n1x; a1y=n1y; a1z=n1z;
            a2x=n2x; a2y=n2y; a2z=n2z;
            a3x=n3x; a3y=n3y; a3z=n3z;
            apx=npx; apy=npy; apz=npz;
        }
    }

    // final publish: inclusive prefix I_s -> slot s+1; identity -> slot 0
    mslot[0] = a1x; mslot[1]  = a1y; mslot[2]  = a1z;
    mslot[3] = a2x; mslot[4]  = a2y; mslot[5]  = a2z;
    mslot[6] = a3x; mslot[7]  = a3y; mslot[8]  = a3z;
    mslot[9] = apx; mslot[10] = apy; mslot[11] = apz;
    if (s == 0) {
        float* id = &mat[c * (SEG + 1) * 12];
        id[0] = 1.f; id[1]  = 0.f; id[2]  = 0.f;
        id[3] = 0.f; id[4]  = 1.f; id[5]  = 0.f;
        id[6] = 0.f; id[7]  = 0.f; id[8]  = 1.f;
        id[9] = 0.f; id[10] = 0.f; id[11] = 0.f;
    }
    __syncthreads();

    // ---- phase 3: cooperative transform + direct coalesced store ----
    // record in segment ss uses exclusive prefix = slot ss (slot0 identity).
    float* gout = out + (size_t)Bbase * (NRES * 3);
    #pragma unroll
    for (int i = 0; i < (CHAINS * NRES) / TPB; ++i) {   // 9 iters
        int e  = tid + i * TPB;
        int cc = e / NRES;
        int j  = e - cc * NRES;
        int ss = j / LSEG;

        const float* rr = &mat[(cc * (SEG + 1) + ss) * 12];
        float qx = buf[e * 3 + 0];
        float qy = buf[e * 3 + 1];
        float qz = buf[e * 3 + 2];
        gout[e * 3 + 0] = fmaf(qx, rr[0], fmaf(qy, rr[3], fmaf(qz, rr[6], rr[9])));
        gout[e * 3 + 1] = fmaf(qx, rr[1], fmaf(qy, rr[4], fmaf(qz, rr[7], rr[10])));
        gout[e * 3 + 2] = fmaf(qx, rr[2], fmaf(qy, rr[5], fmaf(qz, rr[8], rr[11])));
    }
}

extern "C" void kernel_launch(void* const* d_in, const int* in_sizes, int n_in,
                              void* d_out, int out_size)
{
    const float* angles = (const float*)d_in[0];   // (B, 252) f32
    const float* prev   = (const float*)d_in[1];   // (B, 3, 3) f32
    float*       out    = (float*)d_out;           // (B, 126, 3) f32

    const int B = in_sizes[0] / (2 * NRES);        // 65536
    dihedral_kernel<<<B / CHAINS, TPB>>>(angles, prev, out);
}

// round 8
// speedup vs baseline: 1.1000x; 1.1000x over previous
#include <cuda_runtime.h>

// DihedralToCartesian R8: R5's balance point (6 segments x 21 steps, 96 thr,
// 16 chains/CTA) with a shortened serial step:
//  - angle normalization hoisted to parallel phase 0 (buf holds r1, r2)
//  - n-normalize replaced by analytic 1/sin(alpha) scale (safe: w re-normalized
//    every step -> per-step O(eps) error does not compound, unlike R3)
//  - single rsqrt per step (u-normalize) = the only MUFU on the serial chain
//  - cooperative transform + direct coalesced store (no separate copy phase)

#define TPB    96
#define NRES   126
#define CHAINS 16
#define SEG    6
#define LSEG   21             // 21 % 3 == 0 -> canonical entry frame valid

__device__ __forceinline__ float frsqrt(float x) {
    float y;
    asm("rsqrt.approx.f32 %0, %1;" : "=f"(y) : "f"(x));
    return y;
}

__global__ void __launch_bounds__(TPB, 7)
dihedral_kernel(const float* __restrict__ angles,
                const float* __restrict__ prev,
                float* __restrict__ out)
{
    // buf record (3 floats per step): (r1, r2, -) on load -> local points.
    __shared__ float buf[CHAINS * NRES * 3];      // 24192 B
    __shared__ float ex [CHAINS * SEG * 6];       // exit w, v      (2304 B)
    __shared__ float rp [CHAINS * SEG * 12];      // R cols + p     (4608 B)

    const int tid   = threadIdx.x;
    const int c     = tid / SEG;
    const int s     = tid - c * SEG;
    const int Bbase = blockIdx.x * CHAINS;

    const float CA0 = cosf(2.028f), SA0 = sinf(2.028f), B0 = 1.329f;
    const float CA1 = cosf(2.124f), SA1 = sinf(2.124f), B1 = 1.458f;
    const float CA2 = cosf(1.941f), SA2 = sinf(1.941f), B2 = 1.523f;
    const float IS0 = 1.0f / SA0, IS1 = 1.0f / SA1, IS2 = 1.0f / SA2;

    // ---- phase 0: coalesced load + angle normalization (parallel) ----
    const float* gang = angles + (size_t)Bbase * (2 * NRES);
    #pragma unroll
    for (int i = 0; i < (CHAINS * NRES) / TPB; ++i) {   // 21 iters
        int e  = tid + i * TPB;
        int cc = e / NRES;
        int j  = e - cc * NRES;
        int k  = j - (j / 3) * 3;
        float sn = gang[cc * (2 * NRES) + j];
        float co = gang[cc * (2 * NRES) + NRES + j];
        float sa = (k == 0) ? SA0 : (k == 1) ? SA1 : SA2;
        float t  = sa * frsqrt(fmaf(sn, sn, fmaf(co, co, 1e-8f)));
        buf[e * 3 + 0] =  t * co;   // r1
        buf[e * 3 + 1] = -t * sn;   // r2
    }
    __syncthreads();

    // ---- phase 1: LSEG serial steps per segment ----
    float* rec = &buf[(c * NRES + s * LSEG) * 3];
    float px, py, pz, vx, vy, vz, wx, wy, wz;

    // one rsqrt per step; n scaled by analytic 1/sin(alpha[(j-1)%3]) = ISk
    #define STEP(j, CAk, Bk, ISk) do {                                          \
        float r1 = rec[(j) * 3 + 0], r2 = rec[(j) * 3 + 1];                     \
        float nx = (wy * vz - wz * vy) * (ISk);                                 \
        float ny = (wz * vx - wx * vz) * (ISk);                                 \
        float nz = (wx * vy - wy * vx) * (ISk);                                 \
        float mx = wy * nz - wz * ny;                                           \
        float my = wz * nx - wx * nz;                                           \
        float mz = wx * ny - wy * nx;                                           \
        float ux = fmaf(-(CAk), wx, fmaf(r1, mx, r2 * nx));                     \
        float uy = fmaf(-(CAk), wy, fmaf(r1, my, r2 * ny));                     \
        float uz = fmaf(-(CAk), wz, fmaf(r1, mz, r2 * nz));                     \
        px = fmaf((Bk), ux, px);                                                \
        py = fmaf((Bk), uy, py);                                                \
        pz = fmaf((Bk), uz, pz);                                                \
        rec[(j) * 3 + 0] = px;                                                  \
        rec[(j) * 3 + 1] = py;                                                  \
        rec[(j) * 3 + 2] = pz;                                                  \
        float iun = frsqrt(fmaf(ux, ux, fmaf(uy, uy, uz * uz)));                \
        vx = wx; vy = wy; vz = wz;                                              \
        wx = ux * iun; wy = uy * iun; wz = uz * iun;                            \
    } while (0)

    if (s == 0) {
        // real geometry from prev_three; reference-faithful first step
        const float* pp = prev + (size_t)(Bbase + c) * 9;
        float ax = pp[0], ay = pp[1], az = pp[2];
        float bx = pp[3], by = pp[4], bz = pp[5];
        px = pp[6]; py = pp[7]; pz = pp[8];

        float r1 = rec[0], r2 = rec[1];

        float bcx = (bx - px) + 1e-8f;
        float bcy = (by - py) + 1e-8f;
        float bcz = (bz - pz) + 1e-8f;
        float ib = frsqrt(fmaf(bcx, bcx, fmaf(bcy, bcy, bcz * bcz)));
        bcx *= ib; bcy *= ib; bcz *= ib;

        float qx = bx - ax, qy = by - ay, qz = bz - az;
        float nx = fmaf(qy, bcz, fmaf(-qz, bcy, 1e-8f));
        float ny = fmaf(qz, bcx, fmaf(-qx, bcz, 1e-8f));
        float nz = fmaf(qx, bcy, fmaf(-qy, bcx, 1e-8f));
        float in_ = frsqrt(fmaf(nx, nx, fmaf(ny, ny, nz * nz)));
        nx *= in_; ny *= in_; nz *= in_;

        float mx = ny * bcz - nz * bcy;
        float my = nz * bcx - nx * bcz;
        float mz = nx * bcy - ny * bcx;

        float ux = fmaf(CA0, bcx, fmaf(r1, mx, r2 * nx));
        float uy = fmaf(CA0, bcy, fmaf(r1, my, r2 * ny));
        float uz = fmaf(CA0, bcz, fmaf(r1, mz, r2 * nz));

        px = fmaf(B0, ux, px);
        py = fmaf(B0, uy, py);
        pz = fmaf(B0, uz, pz);
        rec[0] = px; rec[1] = py; rec[2] = pz;

        float iun = frsqrt(fmaf(ux, ux, fmaf(uy, uy, uz * uz)));
        vx = -bcx; vy = -bcy; vz = -bcz;
        wx = ux * iun; wy = uy * iun; wz = uz * iun;
    } else {
        // canonical entry frame (boundary geometry constant: i0 % 3 == 0)
        px = 0.f; py = 0.f; pz = 0.f;
        wx = 1.f; wy = 0.f; wz = 0.f;
        vx = -CA2; vy = SA2; vz = 0.f;
        STEP(0, CA0, B0, IS2);
    }
    STEP( 1, CA1, B1, IS0); STEP( 2, CA2, B2, IS1);
    #pragma unroll
    for (int m = 1; m < 7; ++m) {
        STEP(3*m + 0, CA0, B0, IS2);
        STEP(3*m + 1, CA1, B1, IS0);
        STEP(3*m + 2, CA2, B2, IS1);
    }
    #undef STEP

    {   // publish exit directions (exit point is rec[(LSEG-1)*3..])
        float* e6 = &ex[(c * SEG + s) * 6];
        e6[0] = wx; e6[1] = wy; e6[2] = wz;
        e6[3] = vx; e6[4] = vy; e6[5] = vz;
    }
    __syncthreads();

    // ---- phase 2: per-chain sequential compose (16 lanes, 5 iters) ----
    if (tid < CHAINS) {
        const int cc = tid;
        float* r0 = &rp[cc * SEG * 12];
        r0[0] = 1.f; r0[1] = 0.f; r0[2] = 0.f;
        r0[3] = 0.f; r0[4] = 1.f; r0[5] = 0.f;
        r0[6] = 0.f; r0[7] = 0.f; r0[8] = 1.f;
        r0[9] = 0.f; r0[10] = 0.f; r0[11] = 0.f;

        const float* e0 = &ex[cc * SEG * 6];
        const float* q0 = &buf[(cc * NRES + (LSEG - 1)) * 3];
        float pex = q0[0], pey = q0[1], pez = q0[2];
        float wex = e0[0], wey = e0[1], wez = e0[2];
        float vex = e0[3], vey = e0[4], vez = e0[5];

        #pragma unroll
        for (int ss = 1; ss < SEG; ++ss) {
            // Gram-Schmidt basis from entry (w, v)
            float d  = fmaf(vex, wex, fmaf(vey, wey, vez * wez));
            float tx = fmaf(-d, wex, vex);
            float ty = fmaf(-d, wey, vey);
            float tz = fmaf(-d, wez, vez);
            float it = frsqrt(fmaf(tx, tx, fmaf(ty, ty, fmaf(tz, tz, 1e-20f))));
            float g1x = wex,     g1y = wey,     g1z = wez;
            float g2x = tx * it, g2y = ty * it, g2z = tz * it;
            float g3x = g1y * g2z - g1z * g2y;
            float g3y = g1z * g2x - g1x * g2z;
            float g3z = g1x * g2y - g1y * g2x;

            float* rr = &rp[(cc * SEG + ss) * 12];
            rr[0] = g1x; rr[1] = g1y; rr[2] = g1z;
            rr[3] = g2x; rr[4] = g2y; rr[5] = g2z;
            rr[6] = g3x; rr[7] = g3y; rr[8] = g3z;
            rr[9] = pex; rr[10] = pey; rr[11] = pez;

            // chain exit -> next entry (global coords)
            const float* es = &ex[(cc * SEG + ss) * 6];
            const float* qs = &buf[(cc * NRES + ss * LSEG + (LSEG - 1)) * 3];
            float qx = qs[0], qy = qs[1], qz = qs[2];
            float wfx = es[0], wfy = es[1], wfz = es[2];
            float vfx = es[3], vfy = es[4], vfz = es[5];

            float npx = pex + qx * g1x + qy * g2x + qz * g3x;
            float npy = pey + qx * g1y + qy * g2y + qz * g3y;
            float npz = pez + qx * g1z + qy * g2z + qz * g3z;
            wex = wfx * g1x + wfy * g2x + wfz * g3x;
            wey = wfx * g1y + wfy * g2y + wfz * g3y;
            wez = wfx * g1z + wfy * g2z + wfz * g3z;
            vex = vfx * g1x + vfy * g2x + vfz * g3x;
            vey = vfx * g1y + vfy * g2y + vfz * g3y;
            vez = vfx * g1z + vfy * g2z + vfz * g3z;
            pex = npx; pey = npy; pez = npz;
        }
    }
    __syncthreads();

    // ---- phase 3: cooperative transform + direct coalesced store ----
    float* gout = out + (size_t)Bbase * (NRES * 3);
    #pragma unroll
    for (int i = 0; i < (CHAINS * NRES) / TPB; ++i) {   // 21 iters
        int e  = tid + i * TPB;
        int cc = e / NRES;
        int j  = e - cc * NRES;
        int ss = j / LSEG;

        const float* rr = &rp[(cc * SEG + ss) * 12];
        float qx = buf[e * 3 + 0];
        float qy = buf[e * 3 + 1];
        float qz = buf[e * 3 + 2];
        gout[e * 3 + 0] = fmaf(qx, rr[0], fmaf(qy, rr[3], fmaf(qz, rr[6], rr[9])));
        gout[e * 3 + 1] = fmaf(qx, rr[1], fmaf(qy, rr[4], fmaf(qz, rr[7], rr[10])));
        gout[e * 3 + 2] = fmaf(qx, rr[2], fmaf(qy, rr[5], fmaf(qz, rr[8], rr[11])));
    }
}

extern "C" void kernel_launch(void* const* d_in, const int* in_sizes, int n_in,
                              void* d_out, int out_size)
{
    const float* angles = (const float*)d_in[0];   // (B, 252) f32
    const float* prev   = (const float*)d_in[1];   // (B, 3, 3) f32
    float*       out    = (float*)d_out;           // (B, 126, 3) f32

    const int B = in_sizes[0] / (2 * NRES);        // 65536
    dihedral_kernel<<<B / CHAINS, TPB>>>(angles, prev, out);
}

// round 9
// speedup vs baseline: 1.2806x; 1.1642x over previous
#include <cuda_runtime.h>

// DihedralToCartesian R9: R5's structure (best measured: per-thread-segment
// transform with R hoisted to registers + flat coalesced copy) with R8's
// cheap serial step (r1/r2 precomputed in parallel phase 0; n scaled by
// analytic 1/sin(alpha) -- safe since w is re-normalized every step; one
// rsqrt on the serial chain).

#define TPB    96
#define NRES   126
#define CHAINS 16
#define SEG    6
#define LSEG   21             // 21 % 3 == 0 -> canonical entry frame valid

__device__ __forceinline__ float frsqrt(float x) {
    float y;
    asm("rsqrt.approx.f32 %0, %1;" : "=f"(y) : "f"(x));
    return y;
}

__global__ void __launch_bounds__(TPB, 7)
dihedral_kernel(const float* __restrict__ angles,
                const float* __restrict__ prev,
                float* __restrict__ out)
{
    // buf record (3 floats/step): (r1, r2, -) after phase 0 -> local points
    // after phase 1 -> global points after phase 3 (in place).
    __shared__ float buf[CHAINS * NRES * 3];      // 24192 B
    __shared__ float ex [CHAINS * SEG * 9];       // exit p, w, v   (3456 B)
    __shared__ float rp [CHAINS * SEG * 12];      // R cols + p     (4608 B)

    const int tid   = threadIdx.x;
    const int c     = tid / SEG;
    const int s     = tid - c * SEG;
    const int Bbase = blockIdx.x * CHAINS;

    const float CA0 = cosf(2.028f), SA0 = sinf(2.028f), B0 = 1.329f;
    const float CA1 = cosf(2.124f), SA1 = sinf(2.124f), B1 = 1.458f;
    const float CA2 = cosf(1.941f), SA2 = sinf(1.941f), B2 = 1.523f;
    const float IS0 = 1.0f / SA0, IS1 = 1.0f / SA1, IS2 = 1.0f / SA2;

    // ---- phase 0: coalesced load + angle normalization (parallel) ----
    const float* gang = angles + (size_t)Bbase * (2 * NRES);
    #pragma unroll
    for (int i = 0; i < (CHAINS * NRES) / TPB; ++i) {   // 21 iters
        int e  = tid + i * TPB;
        int cc = e / NRES;
        int j  = e - cc * NRES;
        int k  = j - (j / 3) * 3;
        float sn = gang[cc * (2 * NRES) + j];
        float co = gang[cc * (2 * NRES) + NRES + j];
        float sa = (k == 0) ? SA0 : (k == 1) ? SA1 : SA2;
        float t  = sa * frsqrt(fmaf(sn, sn, fmaf(co, co, 1e-8f)));
        buf[e * 3 + 0] =  t * co;   // r1
        buf[e * 3 + 1] = -t * sn;   // r2
    }
    __syncthreads();

    // ---- phase 1: LSEG serial steps per segment ----
    float* rec = &buf[(c * NRES + s * LSEG) * 3];
    float px, py, pz, vx, vy, vz, wx, wy, wz;

    #define STEP(j, CAk, Bk, ISk) do {                                          \
        float r1 = rec[(j) * 3 + 0], r2 = rec[(j) * 3 + 1];                     \
        float nx = (wy * vz - wz * vy) * (ISk);                                 \
        float ny = (wz * vx - wx * vz) * (ISk);                                 \
        float nz = (wx * vy - wy * vx) * (ISk);                                 \
        float mx = wy * nz - wz * ny;                                           \
        float my = wz * nx - wx * nz;                                           \
        float mz = wx * ny - wy * nx;                                           \
        float ux = fmaf(-(CAk), wx, fmaf(r1, mx, r2 * nx));                     \
        float uy = fmaf(-(CAk), wy, fmaf(r1, my, r2 * ny));                     \
        float uz = fmaf(-(CAk), wz, fmaf(r1, mz, r2 * nz));                     \
        px = fmaf((Bk), ux, px);                                                \
        py = fmaf((Bk), uy, py);                                                \
        pz = fmaf((Bk), uz, pz);                                                \
        rec[(j) * 3 + 0] = px;                                                  \
        rec[(j) * 3 + 1] = py;                                                  \
        rec[(j) * 3 + 2] = pz;                                                  \
        float iun = frsqrt(fmaf(ux, ux, fmaf(uy, uy, uz * uz)));                \
        vx = wx; vy = wy; vz = wz;                                              \
        wx = ux * iun; wy = uy * iun; wz = uz * iun;                            \
    } while (0)

    if (s == 0) {
        // real geometry from prev_three; reference-faithful first step
        const float* pp = prev + (size_t)(Bbase + c) * 9;
        float ax = pp[0], ay = pp[1], az = pp[2];
        float bx = pp[3], by = pp[4], bz = pp[5];
        px = pp[6]; py = pp[7]; pz = pp[8];

        float r1 = rec[0], r2 = rec[1];

        float bcx = (bx - px) + 1e-8f;
        float bcy = (by - py) + 1e-8f;
        float bcz = (bz - pz) + 1e-8f;
        float ib = frsqrt(fmaf(bcx, bcx, fmaf(bcy, bcy, bcz * bcz)));
        bcx *= ib; bcy *= ib; bcz *= ib;

        float qx = bx - ax, qy = by - ay, qz = bz - az;
        float nx = fmaf(qy, bcz, fmaf(-qz, bcy, 1e-8f));
        float ny = fmaf(qz, bcx, fmaf(-qx, bcz, 1e-8f));
        float nz = fmaf(qx, bcy, fmaf(-qy, bcx, 1e-8f));
        float in_ = frsqrt(fmaf(nx, nx, fmaf(ny, ny, nz * nz)));
        nx *= in_; ny *= in_; nz *= in_;

        float mx = ny * bcz - nz * bcy;
        float my = nz * bcx - nx * bcz;
        float mz = nx * bcy - ny * bcx;

        float ux = fmaf(CA0, bcx, fmaf(r1, mx, r2 * nx));
        float uy = fmaf(CA0, bcy, fmaf(r1, my, r2 * ny));
        float uz = fmaf(CA0, bcz, fmaf(r1, mz, r2 * nz));

        px = fmaf(B0, ux, px);
        py = fmaf(B0, uy, py);
        pz = fmaf(B0, uz, pz);
        rec[0] = px; rec[1] = py; rec[2] = pz;

        float iun = frsqrt(fmaf(ux, ux, fmaf(uy, uy, uz * uz)));
        vx = -bcx; vy = -bcy; vz = -bcz;
        wx = ux * iun; wy = uy * iun; wz = uz * iun;
    } else {
        // canonical entry frame (boundary geometry constant: i0 % 3 == 0)
        px = 0.f; py = 0.f; pz = 0.f;
        wx = 1.f; wy = 0.f; wz = 0.f;
        vx = -CA2; vy = SA2; vz = 0.f;
        STEP(0, CA0, B0, IS2);
    }
    STEP( 1, CA1, B1, IS0); STEP( 2, CA2, B2, IS1);
    #pragma unroll
    for (int m = 1; m < 7; ++m) {
        STEP(3*m + 0, CA0, B0, IS2);
        STEP(3*m + 1, CA1, B1, IS0);
        STEP(3*m + 2, CA2, B2, IS1);
    }
    #undef STEP

    {   // publish segment exit: last point, final w, final v (local coords)
        float* e9 = &ex[(c * SEG + s) * 9];
        e9[0] = px; e9[1] = py; e9[2] = pz;
        e9[3] = wx; e9[4] = wy; e9[5] = wz;
        e9[6] = vx; e9[7] = vy; e9[8] = vz;
    }
    __syncthreads();

    // ---- phase 2: per-chain sequential compose (16 lanes, 5 iters) ----
    if (tid < CHAINS) {
        const int cc = tid;
        float* r0 = &rp[cc * SEG * 12];
        r0[0] = 1.f; r0[1] = 0.f; r0[2] = 0.f;
        r0[3] = 0.f; r0[4] = 1.f; r0[5] = 0.f;
        r0[6] = 0.f; r0[7] = 0.f; r0[8] = 1.f;
        r0[9] = 0.f; r0[10] = 0.f; r0[11] = 0.f;

        const float* e0 = &ex[cc * SEG * 9];
        float pex = e0[0], pey = e0[1], pez = e0[2];
        float wex = e0[3], wey = e0[4], wez = e0[5];
        float vex = e0[6], vey = e0[7], vez = e0[8];

        #pragma unroll
        for (int ss = 1; ss < SEG; ++ss) {
            // Gram-Schmidt basis from entry (w, v)
            float d  = fmaf(vex, wex, fmaf(vey, wey, vez * wez));
            float tx = fmaf(-d, wex, vex);
            float ty = fmaf(-d, wey, vey);
            float tz = fmaf(-d, wez, vez);
            float it = frsqrt(fmaf(tx, tx, fmaf(ty, ty, fmaf(tz, tz, 1e-20f))));
            float g1x = wex,     g1y = wey,     g1z = wez;
            float g2x = tx * it, g2y = ty * it, g2z = tz * it;
            float g3x = g1y * g2z - g1z * g2y;
            float g3y = g1z * g2x - g1x * g2z;
            float g3z = g1x * g2y - g1y * g2x;

            float* rr = &rp[(cc * SEG + ss) * 12];
            rr[0] = g1x; rr[1] = g1y; rr[2] = g1z;
            rr[3] = g2x; rr[4] = g2y; rr[5] = g2z;
            rr[6] = g3x; rr[7] = g3y; rr[8] = g3z;
            rr[9] = pex; rr[10] = pey; rr[11] = pez;

            // chain exit -> next entry (global coords)
            const float* es = &ex[(cc * SEG + ss) * 9];
            float qx = es[0], qy = es[1], qz = es[2];
            float wfx = es[3], wfy = es[4], wfz = es[5];
            float vfx = es[6], vfy = es[7], vfz = es[8];

            float npx = pex + qx * g1x + qy * g2x + qz * g3x;
            float npy = pey + qx * g1y + qy * g2y + qz * g3y;
            float npz = pez + qx * g1z + qy * g2z + qz * g3z;
            wex = wfx * g1x + wfy * g2x + wfz * g3x;
            wey = wfx * g1y + wfy * g2y + wfz * g3y;
            wez = wfx * g1z + wfy * g2z + wfz * g3z;
            vex = vfx * g1x + vfy * g2x + vfz * g3x;
            vey = vfx * g1y + vfy * g2y + vfz * g3y;
            vez = vfx * g1z + vfy * g2z + vfz * g3z;
            pex = npx; pey = npy; pez = npz;
        }
    }
    __syncthreads();

    // ---- phase 3: per-thread transform of own records (R in registers) ----
    {
        const float* rr = &rp[(c * SEG + s) * 12];
        float g1x = rr[0], g1y = rr[1], g1z = rr[2];
        float g2x = rr[3], g2y = rr[4], g2z = rr[5];
        float g3x = rr[6], g3y = rr[7], g3z = rr[8];
        float ppx = rr[9], ppy = rr[10], ppz = rr[11];
        #pragma unroll 3
        for (int j = 0; j < LSEG; ++j) {
            float qx = rec[j * 3 + 0];
            float qy = rec[j * 3 + 1];
            float qz = rec[j * 3 + 2];
            rec[j * 3 + 0] = fmaf(qx, g1x, fmaf(qy, g2x, fmaf(qz, g3x, ppx)));
            rec[j * 3 + 1] = fmaf(qx, g1y, fmaf(qy, g2y, fmaf(qz, g3y, ppy)));
            rec[j * 3 + 2] = fmaf(qx, g1z, fmaf(qy, g2z, fmaf(qz, g3z, ppz)));
        }
    }
    __syncthreads();

    // ---- phase 4: flat coalesced store (buf layout == global layout) ----
    float* gout = out + (size_t)Bbase * (NRES * 3);
    #pragma unroll
    for (int i = 0; i < (CHAINS * NRES * 3) / TPB; ++i)   // 63 iters
        gout[tid + i * TPB] = buf[tid + i * TPB];
}

extern "C" void kernel_launch(void* const* d_in, const int* in_sizes, int n_in,
                              void* d_out, int out_size)
{
    const float* angles = (const float*)d_in[0];   // (B, 252) f32
    const float* prev   = (const float*)d_in[1];   // (B, 3, 3) f32
    float*       out    = (float*)d_out;           // (B, 126, 3) f32

    const int B = in_sizes[0] / (2 * NRES);        // 65536
    dihedral_kernel<<<B / CHAINS, TPB>>>(angles, prev, out);
}